// round 11
// baseline (speedup 1.0000x reference)
#include <cuda_runtime.h>
#include <cuda_fp16.h>
#include <cstdint>

#define T_STEPS 512
#define BATCH   128
#define IDIM    512
#define HDIM    512
#define BH      (BATCH * HDIM)   /* 65536 */

__device__ __forceinline__ uint32_t pack_h2(float a, float b) {
    __half2 h = __floats2half2_rn(a, b);
    return *reinterpret_cast<uint32_t*>(&h);
}
__device__ __forceinline__ float tanh_fast(float x) {
    float e = __expf(2.0f * x);
    return 1.0f - __fdividef(2.0f, e + 1.0f);
}
__device__ __forceinline__ void mma_f16(float c[4], const uint32_t a[4],
                                        uint32_t b0, uint32_t b1) {
    asm volatile(
        "mma.sync.aligned.m16n8k16.row.col.f32.f16.f16.f32 "
        "{%0,%1,%2,%3}, {%4,%5,%6,%7}, {%8,%9}, {%0,%1,%2,%3};"
        : "+f"(c[0]), "+f"(c[1]), "+f"(c[2]), "+f"(c[3])
        : "r"(a[0]), "r"(a[1]), "r"(a[2]), "r"(a[3]), "r"(b0), "r"(b1));
}
__device__ __forceinline__ uint32_t smem_u32(const void* p) {
    return (uint32_t)__cvta_generic_to_shared(p);
}
__device__ __forceinline__ void cp16(uint32_t dst, const void* src) {
    asm volatile("cp.async.cg.shared.global [%0], [%1], 16;" :: "r"(dst), "l"(src));
}
__device__ __forceinline__ uint32_t mapa_rank(uint32_t addr, uint32_t rank) {
    uint32_t r;
    asm("mapa.shared::cluster.u32 %0, %1, %2;" : "=r"(r) : "r"(addr), "r"(rank));
    return r;
}
__device__ __forceinline__ void st_cluster_u32(uint32_t addr, uint32_t v) {
    asm volatile("st.shared::cluster.u32 [%0], %1;" :: "r"(addr), "r"(v) : "memory");
}

// ============================================================================
// Kernel 1: xw = x @ W_ih^T + bias. fp32 cp.async pipeline (R2-proven tiles),
// fp16 fragments packed at load time, m16n8k16 (half the MMA count),
// fp32 accumulate. Tile 128x64, BK=16, 32 iters, double-buffered.
// ============================================================================
__global__ __launch_bounds__(256) void xw_gemm(const float* __restrict__ x,
                                               const float* __restrict__ w_ih,
                                               const float* __restrict__ bias,
                                               float* __restrict__ out) {
    __shared__ __align__(16) float Xs[2][128][20];
    __shared__ __align__(16) float Ws[2][64][20];

    const int tid  = threadIdx.x;
    const int warp = tid >> 5, lane = tid & 31;
    const int g = lane >> 2, tg = lane & 3;

    const int nt = blockIdx.x & 7;
    const int mt = blockIdx.x >> 3;
    const int m0 = mt * 128, n0 = nt * 64;
    const int wm = warp >> 1, wn = warp & 1;

    float c[2][4][4];
#pragma unroll
    for (int i = 0; i < 2; i++)
#pragma unroll
        for (int nb = 0; nb < 4; nb++)
#pragma unroll
            for (int r = 0; r < 4; r++) c[i][nb][r] = 0.f;

    const int xr = tid >> 2, xc = (tid & 3) * 4;
    const float* xs0  = x    + (size_t)(m0 + xr) * IDIM + xc;
    const float* xs1  = x    + (size_t)(m0 + xr + 64) * IDIM + xc;
    const float* wsrc = w_ih + (size_t)(n0 + xr) * IDIM + xc;

    const uint32_t dX0[2] = { smem_u32(&Xs[0][xr][xc]),      smem_u32(&Xs[1][xr][xc]) };
    const uint32_t dX1[2] = { smem_u32(&Xs[0][xr + 64][xc]), smem_u32(&Xs[1][xr + 64][xc]) };
    const uint32_t dW[2]  = { smem_u32(&Ws[0][xr][xc]),      smem_u32(&Ws[1][xr][xc]) };

    cp16(dX0[0], xs0);
    cp16(dX1[0], xs1);
    if (xr < 64) cp16(dW[0], wsrc);
    asm volatile("cp.async.commit_group;");

    const int c0 = tg * 2;      // k halves {2tg, 2tg+1}
    const int c1 = tg * 2 + 8;  // k halves {2tg+8, 2tg+9}

    for (int it = 0; it < 32; ++it) {
        const int s = it & 1;
        if (it < 31) {
            const int kt = (it + 1) * 16;
            cp16(dX0[s ^ 1], xs0 + kt);
            cp16(dX1[s ^ 1], xs1 + kt);
            if (xr < 64) cp16(dW[s ^ 1], wsrc + kt);
            asm volatile("cp.async.commit_group;");
            asm volatile("cp.async.wait_group 1;");
        } else {
            asm volatile("cp.async.wait_group 0;");
        }
        __syncthreads();

        uint32_t a[2][4];
#pragma unroll
        for (int i = 0; i < 2; i++) {
            const int row = wm * 32 + i * 16 + g;
            float2 v00 = *(const float2*)&Xs[s][row][c0];
            float2 v10 = *(const float2*)&Xs[s][row + 8][c0];
            float2 v01 = *(const float2*)&Xs[s][row][c1];
            float2 v11 = *(const float2*)&Xs[s][row + 8][c1];
            a[i][0] = pack_h2(v00.x, v00.y);
            a[i][1] = pack_h2(v10.x, v10.y);
            a[i][2] = pack_h2(v01.x, v01.y);
            a[i][3] = pack_h2(v11.x, v11.y);
        }
        uint32_t bf[4][2];
#pragma unroll
        for (int nb = 0; nb < 4; nb++) {
            const int row = wn * 32 + nb * 8 + g;
            float2 w0 = *(const float2*)&Ws[s][row][c0];
            float2 w1 = *(const float2*)&Ws[s][row][c1];
            bf[nb][0] = pack_h2(w0.x, w0.y);
            bf[nb][1] = pack_h2(w1.x, w1.y);
        }
#pragma unroll
        for (int i = 0; i < 2; i++)
#pragma unroll
            for (int nb = 0; nb < 4; nb++)
                mma_f16(c[i][nb], a[i], bf[nb][0], bf[nb][1]);
        __syncthreads();
    }

#pragma unroll
    for (int i = 0; i < 2; i++)
#pragma unroll
        for (int nb = 0; nb < 4; nb++) {
            int row = m0 + wm * 32 + i * 16 + g;
            int col = n0 + wn * 32 + nb * 8 + tg * 2;
            float b0v = bias[col], b1v = bias[col + 1];
            out[(size_t)row * HDIM + col]           = c[i][nb][0] + b0v;
            out[(size_t)row * HDIM + col + 1]       = c[i][nb][1] + b1v;
            out[(size_t)(row + 8) * HDIM + col]     = c[i][nb][2] + b0v;
            out[(size_t)(row + 8) * HDIM + col + 1] = c[i][nb][3] + b1v;
        }
}

// ============================================================================
// Kernel 2: persistent recurrence — R8 structure with ONE-PHASE reduction
// (Red[8][544], single __syncthreads). All sync/push/fragment code identical
// to the proven R8 kernel.
// ============================================================================
__global__ __launch_bounds__(256) __cluster_dims__(8, 1, 1)
void rnn_step_kernel(const float* __restrict__ w_hh, float* __restrict__ out) {
    __shared__ uint32_t Hs[2][8][256];              // 16 KB
    __shared__ __align__(16) float Red[8][544];     // 17 KB, pitch 68

    const int tid  = threadIdx.x;
    const int warp = tid >> 5, lane = tid & 31;
    const int g = lane >> 2, tg = lane & 3;
    const int j = blockIdx.x >> 3;
    const int i = blockIdx.x & 7;

    uint32_t aw[4][4][4];
#pragma unroll
    for (int nb = 0; nb < 4; nb++)
#pragma unroll
        for (int k16 = 0; k16 < 4; k16++) {
            const int r0w = i * 64 + nb * 16 + g;
            const int r1w = r0w + 8;
            const int col = warp * 64 + k16 * 16 + tg * 2;
            const float* w0 = w_hh + (size_t)r0w * HDIM + col;
            const float* w1 = w_hh + (size_t)r1w * HDIM + col;
            aw[nb][k16][0] = pack_h2(w0[0], w0[1]);
            aw[nb][k16][1] = pack_h2(w1[0], w1[1]);
            aw[nb][k16][2] = pack_h2(w0[8], w0[9]);
            aw[nb][k16][3] = pack_h2(w1[8], w1[9]);
        }

    const int m = warp;
    const int n = lane * 2;
    const size_t obase = (size_t)(j * 8 + m) * HDIM + i * 64 + n;

    const uint32_t hs_word = (uint32_t)(m * 256 + ((i * 32 + lane) ^ (m * 4)));
    const uint32_t hs_addr0 = smem_u32(&Hs[0][0][0]) + hs_word * 4;

    uint32_t hpush[8];
#pragma unroll
    for (int r = 0; r < 8; r++) hpush[r] = mapa_rank(hs_addr0, (i + r) & 7);

    asm volatile("barrier.cluster.arrive.aligned;" ::: "memory");
    asm volatile("barrier.cluster.wait.aligned;" ::: "memory");

    float2 xwv = *(const float2*)(out + obase);

    for (int t = 0; t < T_STEPS; t++) {
        float r0, r1;
        if (t == 0) {
            r0 = tanh_fast(xwv.x);
            r1 = tanh_fast(xwv.y);
        } else {
            asm volatile("barrier.cluster.wait.aligned;" ::: "memory");
            const uint32_t* hb = &Hs[(t + 1) & 1][0][0];

            float c[4][4];
#pragma unroll
            for (int nb = 0; nb < 4; nb++)
#pragma unroll
                for (int r = 0; r < 4; r++) c[nb][r] = 0.f;

#pragma unroll
            for (int k16 = 0; k16 < 4; k16++) {
                const int base = warp * 32 + k16 * 8;
                uint32_t b0 = hb[g * 256 + ((base + tg) ^ (g * 4))];
                uint32_t b1 = hb[g * 256 + ((base + tg + 4) ^ (g * 4))];
#pragma unroll
                for (int nb = 0; nb < 4; nb++)
                    mma_f16(c[nb], aw[nb][k16], b0, b1);
            }

            // ---- ONE-PHASE cross-warp K reduction ----
            {
                float* rp = Red[warp];
#pragma unroll
                for (int nb = 0; nb < 4; nb++)
#pragma unroll
                    for (int r = 0; r < 4; r++) {
                        int idx = (tg * 2 + (r & 1)) * 68 + nb * 16 + g + ((r & 2) << 2);
                        rp[idx] = c[nb][r];
                    }
            }
            __syncthreads();

            float s0 = 0.f, s1 = 0.f;
#pragma unroll
            for (int w = 0; w < 8; w++) {
                float2 v = *(const float2*)&Red[w][m * 68 + n];
                s0 += v.x;
                s1 += v.y;
            }
            r0 = tanh_fast(xwv.x + s0);
            r1 = tanh_fast(xwv.y + s1);
        }

        if (t < T_STEPS - 1) {
            const uint32_t pv = pack_h2(r0, r1);
            const uint32_t boff = (t & 1) ? 8192u : 0u;
#pragma unroll
            for (int r = 0; r < 8; r++) st_cluster_u32(hpush[r] + boff, pv);
            asm volatile("barrier.cluster.arrive.aligned;" ::: "memory");
        }

        *(float2*)(out + (size_t)t * BH + obase) = make_float2(r0, r1);
        if (t == T_STEPS - 1) {
            *(float2*)(out + (size_t)T_STEPS * BH + obase) = make_float2(r0, r1);
        } else {
            xwv = *(const float2*)(out + (size_t)(t + 1) * BH + obase);
        }
    }

    asm volatile("barrier.cluster.arrive.aligned;" ::: "memory");
    asm volatile("barrier.cluster.wait.aligned;" ::: "memory");
}

extern "C" void kernel_launch(void* const* d_in, const int* in_sizes, int n_in,
                              void* d_out, int out_size) {
    (void)in_sizes; (void)n_in; (void)out_size;
    const float* x    = (const float*)d_in[0];
    const float* w_ih = (const float*)d_in[1];
    const float* w_hh = (const float*)d_in[2];
    const float* b    = (const float*)d_in[3];
    float* out = (float*)d_out;

    xw_gemm<<<4096, 256>>>(x, w_ih, b, out);
    rnn_step_kernel<<<128, 256>>>(w_hh, out);
}